// round 15
// baseline (speedup 1.0000x reference)
#include <cuda_runtime.h>
#include <cuda_bf16.h>
#include <cstdint>

constexpr int L_  = 4;
constexpr int CB_ = 256;
constexpr int D_  = 512;
constexpr int B_  = 16;
constexpr int T_  = 4096;
constexpr int N_BT = B_ * T_;
constexpr float EPS_ = 1e-5f;

__device__ float g_z1[(size_t)B_ * D_ * T_];
__device__ float g_z2[(size_t)B_ * D_ * T_];
__device__ __align__(16) __nv_bfloat16 g_xbh[(size_t)B_ * CB_ * T_];
__device__ __align__(16) __nv_bfloat16 g_xbl[(size_t)B_ * CB_ * T_];
__device__ __align__(16) __nv_bfloat16 g_w1s[L_ * D_ * CB_];
__device__ __align__(16) __nv_bfloat16 g_w2s[L_ * CB_ * D_];
__device__ float g_wds[L_ * D_ * 3];
__device__ float g_s1[L_ * D_];
__device__ float g_q1[L_ * D_];
__device__ float g_s2[L_ * D_];
__device__ float g_q2[L_ * D_];

__device__ __forceinline__ unsigned smem_u32(const void* p) {
    return (unsigned)__cvta_generic_to_shared(p);
}
__device__ __forceinline__ void ldsm4(unsigned* r, const void* p) {
    unsigned a = smem_u32(p);
    asm volatile("ldmatrix.sync.aligned.m8n8.x4.shared.b16 {%0,%1,%2,%3}, [%4];"
                 : "=r"(r[0]), "=r"(r[1]), "=r"(r[2]), "=r"(r[3]) : "r"(a));
}
__device__ __forceinline__ void ldsm4t(unsigned* r, const void* p) {
    unsigned a = smem_u32(p);
    asm volatile("ldmatrix.sync.aligned.m8n8.x4.trans.shared.b16 {%0,%1,%2,%3}, [%4];"
                 : "=r"(r[0]), "=r"(r[1]), "=r"(r[2]), "=r"(r[3]) : "r"(a));
}
__device__ __forceinline__ void mma16816(float* c, const unsigned* a, unsigned b0, unsigned b1) {
    asm volatile(
        "mma.sync.aligned.m16n8k16.row.col.f32.bf16.bf16.f32 "
        "{%0,%1,%2,%3},{%4,%5,%6,%7},{%8,%9},{%0,%1,%2,%3};"
        : "+f"(c[0]), "+f"(c[1]), "+f"(c[2]), "+f"(c[3])
        : "r"(a[0]), "r"(a[1]), "r"(a[2]), "r"(a[3]), "r"(b0), "r"(b1));
}
__device__ __forceinline__ void cp16(void* dst, const void* src) {
    unsigned d = smem_u32(dst);
    asm volatile("cp.async.ca.shared.global [%0], [%1], 16;" :: "r"(d), "l"(src) : "memory");
}
__device__ __forceinline__ void cp_commit() { asm volatile("cp.async.commit_group;" ::: "memory"); }
__device__ __forceinline__ void cp_wait0()  { asm volatile("cp.async.wait_group 0;" ::: "memory"); }
__device__ __forceinline__ void split_hilo(float v, __nv_bfloat16& h, __nv_bfloat16& l) {
    h = __float2bfloat16(v);
    l = __float2bfloat16(v - __bfloat162float(h));
}
__device__ __forceinline__ uint32_t packbf(__nv_bfloat16 a, __nv_bfloat16 b) {
    __nv_bfloat162 t; t.x = a; t.y = b;
    return *reinterpret_cast<uint32_t*>(&t);
}

__global__ void prep_kernel(const float* __restrict__ w1,
                            const float* __restrict__ w2,
                            const float* __restrict__ wd) {
    int i = blockIdx.x * blockDim.x + threadIdx.x;
    constexpr int n1 = L_ * D_ * CB_;
    constexpr int n2 = L_ * CB_ * D_;
    constexpr int n3 = L_ * D_ * 3;
    constexpr int n4 = L_ * D_;
    if (i < n1) {
        float v = w1[i];
        g_w1s[i] = __float2bfloat16(v > 0.f ? 1.f : (v < 0.f ? -1.f : 0.f));
    } else if (i < n1 + n2) {
        float v = w2[i - n1];
        g_w2s[i - n1] = __float2bfloat16(v > 0.f ? 1.f : (v < 0.f ? -1.f : 0.f));
    } else if (i < n1 + n2 + n3) {
        float v = wd[i - n1 - n2];
        g_wds[i - n1 - n2] = v > 0.f ? 1.f : (v < 0.f ? -1.f : 0.f);
    } else if (i < n1 + n2 + n3 + 4 * n4) {
        int j = i - (n1 + n2 + n3);
        int which = j / n4, k = j % n4;
        if (which == 0) g_s1[k] = 0.f;
        else if (which == 1) g_q1[k] = 0.f;
        else if (which == 2) g_s2[k] = 0.f;
        else g_q2[k] = 0.f;
    }
}

// MODE 0: gemm1 L0 (fp32 in) | 1: gemm1 L>0 (planes in, cp.async) | 2: gemm2 mid (planes out) | 3: gemm2 last (fp32+resid)
constexpr int BM = 64, BN = 256, BK = 32;
constexpr int WPITCH = 40, XPITCH = 264;
constexpr int WS_ELEMS = BM * WPITCH;   // 2560
constexpr int XT_ELEMS = BK * XPITCH;   // 8448
constexpr size_t GEMM_SMEM = (size_t)(2 * WS_ELEMS + 4 * XT_ELEMS) * sizeof(__nv_bfloat16);

template<int MODE>
__global__ void __launch_bounds__(256, 2) gemm_kernel(
    const float* __restrict__ Xext, float* __restrict__ Oext,
    const float* __restrict__ bias, const float* __restrict__ aptr,
    const float* __restrict__ gch, const float* __restrict__ bech, int layer) {
    constexpr bool FIRST = (MODE <= 1);
    constexpr int Cin  = FIRST ? CB_ : D_;
    constexpr int Cout = FIRST ? D_ : CB_;
    constexpr int NITER = Cin / BK;
    const __nv_bfloat16* __restrict__ W =
        (FIRST ? g_w1s : g_w2s) + (size_t)layer * Cin * Cout;

    extern __shared__ __align__(16) char sm_raw[];
    __nv_bfloat16* WS = reinterpret_cast<__nv_bfloat16*>(sm_raw);
    __nv_bfloat16* XH = WS + 2 * WS_ELEMS;
    __nv_bfloat16* XL = XH + 2 * XT_ELEMS;

    const int b  = blockIdx.z;
    const int m0 = blockIdx.y * BM;
    const int t0 = blockIdx.x * BN;
    const int tid  = threadIdx.x;
    const int warp = tid >> 5, lane = tid & 31;
    const int wm = (warp & 1) * 32;       // 2 warps along M
    const int wn = (warp >> 1) * 64;      // 4 warps along N

    const int wrow = tid >> 2, wcol = (tid & 3) * 8;      // W producer (1 cp16)
    const int krow = tid >> 3, xcol = (tid & 7) * 32;     // X fp32 producer (8 float4)
    const int prow = tid >> 4, pcol = (tid & 15) * 16;    // X plane producer (+16 row stride)

    const size_t xoff = (size_t)b * Cin * T_ + t0;
    const float* Xf = (MODE == 0) ? Xext + xoff : g_z2 + xoff;
    const __nv_bfloat16* Xph = g_xbh + xoff;
    const __nv_bfloat16* Xpl = g_xbl + xoff;

    float acc[2][8][4];
    #pragma unroll
    for (int i = 0; i < 2; i++)
        #pragma unroll
        for (int j = 0; j < 8; j++)
            #pragma unroll
            for (int r = 0; r < 4; r++) acc[i][j][r] = 0.f;

    const int grp = lane >> 3, l8 = lane & 7;
    const int bk_row = (grp & 1) * 8 + l8;
    const int bn_off = (grp >> 1) * 8;

    float4 xf[8];
    float2 ssreg;
    constexpr float invN = 1.f / (float)N_BT;

    auto cp_stage = [&](int c0, int p) {   // async parts: W always, X when MODE1
        cp16(&WS[p * WS_ELEMS + wrow * WPITCH + wcol],
             W + (size_t)(m0 + wrow) * Cin + c0 + wcol);
        if (MODE == 1) {
            #pragma unroll
            for (int h = 0; h < 2; h++) {
                const int row = prow + h * 16;
                const __nv_bfloat16* sh = Xph + (size_t)(c0 + row) * T_ + pcol;
                const __nv_bfloat16* sl = Xpl + (size_t)(c0 + row) * T_ + pcol;
                __nv_bfloat16* dh = &XH[p * XT_ELEMS + row * XPITCH + pcol];
                __nv_bfloat16* dl = &XL[p * XT_ELEMS + row * XPITCH + pcol];
                cp16(dh, sh); cp16(dh + 8, sh + 8);
                cp16(dl, sl); cp16(dl + 8, sl + 8);
            }
        }
        cp_commit();
    };
    auto issue_x = [&](int c0) {           // fp32 X prefetch (MODE 0/2/3)
        if (MODE == 1) return;
        const int c = c0 + krow;
        #pragma unroll
        for (int q = 0; q < 8; q++)
            xf[q] = *reinterpret_cast<const float4*>(Xf + (size_t)c * T_ + xcol + q * 4);
        if (MODE >= 2) {
            ssreg.x = g_s2[layer * D_ + c];
            ssreg.y = g_q2[layer * D_ + c];
        }
    };
    auto commit_x = [&](int c0, int p) {   // transform + split + STS (MODE 0/2/3)
        if (MODE == 1) return;
        float s = 1.f, sh = 0.f;
        if (MODE >= 2) {
            const int c = c0 + krow;
            const float mean = ssreg.x * invN;
            const float var  = ssreg.y * invN - mean * mean;
            s  = __ldg(gch + c) * rsqrtf(var + EPS_);
            sh = __ldg(bech + c) - mean * s;
        }
        uint32_t* ph = reinterpret_cast<uint32_t*>(&XH[p * XT_ELEMS + krow * XPITCH + xcol]);
        uint32_t* pl = reinterpret_cast<uint32_t*>(&XL[p * XT_ELEMS + krow * XPITCH + xcol]);
        #pragma unroll
        for (int q = 0; q < 8; q++) {
            float v0 = xf[q].x, v1 = xf[q].y, v2 = xf[q].z, v3 = xf[q].w;
            if (MODE >= 2) {
                v0 = fmaf(s, v0, sh); v1 = fmaf(s, v1, sh);
                v2 = fmaf(s, v2, sh); v3 = fmaf(s, v3, sh);
            }
            __nv_bfloat16 h0, h1, h2, h3, l0, l1, l2, l3;
            split_hilo(v0, h0, l0); split_hilo(v1, h1, l1);
            split_hilo(v2, h2, l2); split_hilo(v3, h3, l3);
            ph[2 * q] = packbf(h0, h1); ph[2 * q + 1] = packbf(h2, h3);
            pl[2 * q] = packbf(l0, l1); pl[2 * q + 1] = packbf(l2, l3);
        }
    };
    auto compute = [&](int p) {
        #pragma unroll
        for (int kk = 0; kk < 2; kk++) {
            const int k0 = kk * 16;
            unsigned a[2][4];
            #pragma unroll
            for (int mf = 0; mf < 2; mf++)
                ldsm4(a[mf], &WS[p * WS_ELEMS + (wm + mf * 16 + (lane & 15)) * WPITCH +
                                 k0 + (lane >> 4) * 8]);
            #pragma unroll
            for (int nb = 0; nb < 4; nb++) {
                unsigned bq[4];
                const int baddr = (k0 + bk_row) * XPITCH + wn + nb * 16 + bn_off;
                ldsm4t(bq, &XH[p * XT_ELEMS + baddr]);
                #pragma unroll
                for (int mf = 0; mf < 2; mf++) {
                    mma16816(acc[mf][2 * nb],     a[mf], bq[0], bq[1]);
                    mma16816(acc[mf][2 * nb + 1], a[mf], bq[2], bq[3]);
                }
                ldsm4t(bq, &XL[p * XT_ELEMS + baddr]);
                #pragma unroll
                for (int mf = 0; mf < 2; mf++) {
                    mma16816(acc[mf][2 * nb],     a[mf], bq[0], bq[1]);
                    mma16816(acc[mf][2 * nb + 1], a[mf], bq[2], bq[3]);
                }
            }
        }
    };

    cp_stage(0, 0);
    issue_x(0);
    commit_x(0, 0);
    cp_wait0();
    __syncthreads();
    int p = 0;
    #pragma unroll 1
    for (int it = 0; it < NITER; ++it) {
        if (it + 1 < NITER) {
            cp_stage((it + 1) * BK, p ^ 1);
            issue_x((it + 1) * BK);
        }
        compute(p);
        if (it + 1 < NITER) {
            commit_x((it + 1) * BK, p ^ 1);
            cp_wait0();
            __syncthreads();
        }
        p ^= 1;
    }

    float av = 0.f;
    if (FIRST) av = __ldg(aptr);
    #pragma unroll
    for (int mf = 0; mf < 2; mf++) {
        #pragma unroll
        for (int half = 0; half < 2; half++) {
            const int row = m0 + wm + mf * 16 + (lane >> 2) + half * 8;
            const float bv = __ldg(bias + row);
            const size_t obase = ((size_t)b * Cout + row) * T_ + t0;
            float ps = 0.f, pss = 0.f;
            #pragma unroll
            for (int nf = 0; nf < 8; nf++) {
                const int col = wn / 64 * 64 + nf * 8 + (lane & 3) * 2;
                float v0 = acc[mf][nf][half * 2 + 0] + bv;
                float v1 = acc[mf][nf][half * 2 + 1] + bv;
                const int gcol = wn + nf * 8 + (lane & 3) * 2;
                (void)col;
                if (FIRST) {
                    v0 = v0 >= 0.f ? v0 : av * v0;
                    v1 = v1 >= 0.f ? v1 : av * v1;
                    ps += v0 + v1;
                    pss += fmaf(v0, v0, v1 * v1);
                    float2 o2; o2.x = v0; o2.y = v1;
                    *reinterpret_cast<float2*>(g_z1 + obase + gcol) = o2;
                } else if (MODE == 2) {
                    __nv_bfloat16 ha, hb, la, lb;
                    split_hilo(v0, ha, la);
                    split_hilo(v1, hb, lb);
                    *reinterpret_cast<uint32_t*>(g_xbh + obase + gcol) = packbf(ha, hb);
                    *reinterpret_cast<uint32_t*>(g_xbl + obase + gcol) = packbf(la, lb);
                } else {
                    const float2 rv = *reinterpret_cast<const float2*>(Xext + obase + gcol);
                    float2 o2; o2.x = v0 + rv.x; o2.y = v1 + rv.y;
                    *reinterpret_cast<float2*>(Oext + obase + gcol) = o2;
                }
            }
            if (FIRST) {
                ps  += __shfl_xor_sync(0xffffffffu, ps, 1);
                ps  += __shfl_xor_sync(0xffffffffu, ps, 2);
                pss += __shfl_xor_sync(0xffffffffu, pss, 1);
                pss += __shfl_xor_sync(0xffffffffu, pss, 2);
                if ((lane & 3) == 0) {
                    atomicAdd(&g_s1[layer * D_ + row], ps);
                    atomicAdd(&g_q1[layer * D_ + row], pss);
                }
            }
        }
    }
}

template<int DIL>
__global__ void __launch_bounds__(512) dwconv_kernel(const float* __restrict__ bdl,
                                                     const float* __restrict__ aptr,
                                                     const float* __restrict__ gch,
                                                     const float* __restrict__ bech,
                                                     int layer) {
    const int d = blockIdx.x, b = blockIdx.y;
    __shared__ float s[16 + T_];
    const float* __restrict__ zin = g_z1 + ((size_t)b * D_ + d) * T_;
    float* __restrict__ zo = g_z2 + ((size_t)b * D_ + d) * T_;

    constexpr float invN = 1.f / (float)N_BT;
    const float mean = g_s1[layer * D_ + d] * invN;
    const float var  = g_q1[layer * D_ + d] * invN - mean * mean;
    const float sc = __ldg(gch + d) * rsqrtf(var + EPS_);
    const float sh = __ldg(bech + d) - mean * sc;

    const int t0 = threadIdx.x * 8;
    #pragma unroll
    for (int h = 0; h < 2; h++) {
        float4 v = *reinterpret_cast<const float4*>(zin + t0 + h * 4);
        float4 w;
        w.x = fmaf(sc, v.x, sh); w.y = fmaf(sc, v.y, sh);
        w.z = fmaf(sc, v.z, sh); w.w = fmaf(sc, v.w, sh);
        *reinterpret_cast<float4*>(&s[16 + t0 + h * 4]) = w;
    }
    if (threadIdx.x < 4)
        *reinterpret_cast<float4*>(&s[threadIdx.x * 4]) = make_float4(0.f, 0.f, 0.f, 0.f);
    __syncthreads();

    const float w0 = g_wds[(layer * D_ + d) * 3 + 0];
    const float w1 = g_wds[(layer * D_ + d) * 3 + 1];
    const float w2 = g_wds[(layer * D_ + d) * 3 + 2];
    const float bb = __ldg(bdl + d);
    const float av = __ldg(aptr);

    float r[24];
    #pragma unroll
    for (int q = 0; q < 6; q++)
        *reinterpret_cast<float4*>(&r[q * 4]) =
            *reinterpret_cast<const float4*>(&s[t0 + q * 4]);

    float vv[8];
    float ps = 0.f, pss = 0.f;
    #pragma unroll
    for (int j = 0; j < 8; j++) {
        float acc = bb;
        acc = fmaf(w0, r[16 + j - 2 * DIL], acc);
        acc = fmaf(w1, r[16 + j - DIL], acc);
        acc = fmaf(w2, r[16 + j], acc);
        float v = acc >= 0.f ? acc : av * acc;
        vv[j] = v;
        ps += v;
        pss = fmaf(v, v, pss);
    }
    #pragma unroll
    for (int h = 0; h < 2; h++) {
        float4 o4;
        o4.x = vv[h * 4]; o4.y = vv[h * 4 + 1]; o4.z = vv[h * 4 + 2]; o4.w = vv[h * 4 + 3];
        *reinterpret_cast<float4*>(zo + t0 + h * 4) = o4;
    }

    #pragma unroll
    for (int o = 16; o; o >>= 1) {
        ps  += __shfl_down_sync(0xffffffffu, ps, o);
        pss += __shfl_down_sync(0xffffffffu, pss, o);
    }
    __shared__ float ssum[16], ssq[16];
    const int warp = threadIdx.x >> 5, lane = threadIdx.x & 31;
    if (lane == 0) { ssum[warp] = ps; ssq[warp] = pss; }
    __syncthreads();
    if (warp == 0) {
        ps  = lane < 16 ? ssum[lane] : 0.f;
        pss = lane < 16 ? ssq[lane] : 0.f;
        #pragma unroll
        for (int o = 8; o; o >>= 1) {
            ps  += __shfl_down_sync(0xffffffffu, ps, o);
            pss += __shfl_down_sync(0xffffffffu, pss, o);
        }
        if (lane == 0) {
            atomicAdd(&g_s2[layer * D_ + d], ps);
            atomicAdd(&g_q2[layer * D_ + d], pss);
        }
    }
}

extern "C" void kernel_launch(void* const* d_in, const int* in_sizes, int n_in,
                              void* d_out, int out_size) {
    (void)in_sizes; (void)n_in; (void)out_size;
    const float* x   = (const float*)d_in[0];
    const float* w1  = (const float*)d_in[1];
    const float* b1  = (const float*)d_in[2];
    const float* a1  = (const float*)d_in[3];
    const float* g1  = (const float*)d_in[4];
    const float* be1 = (const float*)d_in[5];
    const float* wd  = (const float*)d_in[6];
    const float* bd  = (const float*)d_in[7];
    const float* a2  = (const float*)d_in[8];
    const float* g2  = (const float*)d_in[9];
    const float* be2 = (const float*)d_in[10];
    const float* w2  = (const float*)d_in[11];
    const float* b2  = (const float*)d_in[12];
    float* out = (float*)d_out;

    static bool attr_done = false;
    if (!attr_done) {
        cudaFuncSetAttribute(gemm_kernel<0>, cudaFuncAttributeMaxDynamicSharedMemorySize, (int)GEMM_SMEM);
        cudaFuncSetAttribute(gemm_kernel<1>, cudaFuncAttributeMaxDynamicSharedMemorySize, (int)GEMM_SMEM);
        cudaFuncSetAttribute(gemm_kernel<2>, cudaFuncAttributeMaxDynamicSharedMemorySize, (int)GEMM_SMEM);
        cudaFuncSetAttribute(gemm_kernel<3>, cudaFuncAttributeMaxDynamicSharedMemorySize, (int)GEMM_SMEM);
        attr_done = true;
    }

    constexpr int prep_total = L_ * D_ * CB_ + L_ * CB_ * D_ + L_ * D_ * 3 + 4 * L_ * D_;
    prep_kernel<<<(prep_total + 255) / 256, 256>>>(w1, w2, wd);

    dim3 gg1(T_ / BN, D_ / BM, B_);    // 16 x 8 x 16
    dim3 gg2(T_ / BN, CB_ / BM, B_);   // 16 x 4 x 16
    dim3 gdw(D_, B_);

    for (int i = 0; i < L_; i++) {
        if (i == 0)
            gemm_kernel<0><<<gg1, 256, GEMM_SMEM>>>(x, nullptr, b1, a1, nullptr, nullptr, 0);
        else
            gemm_kernel<1><<<gg1, 256, GEMM_SMEM>>>(nullptr, nullptr, b1 + i * D_, a1 + i, nullptr, nullptr, i);
        switch (i) {
            case 0: dwconv_kernel<1><<<gdw, 512>>>(bd + i * D_, a2 + i, g1 + i * D_, be1 + i * D_, i); break;
            case 1: dwconv_kernel<2><<<gdw, 512>>>(bd + i * D_, a2 + i, g1 + i * D_, be1 + i * D_, i); break;
            case 2: dwconv_kernel<4><<<gdw, 512>>>(bd + i * D_, a2 + i, g1 + i * D_, be1 + i * D_, i); break;
            default: dwconv_kernel<8><<<gdw, 512>>>(bd + i * D_, a2 + i, g1 + i * D_, be1 + i * D_, i); break;
        }
        if (i < L_ - 1)
            gemm_kernel<2><<<gg2, 256, GEMM_SMEM>>>(nullptr, nullptr, b2 + i * CB_, nullptr, g2 + i * D_, be2 + i * D_, i);
        else
            gemm_kernel<3><<<gg2, 256, GEMM_SMEM>>>(x, out, b2 + i * CB_, nullptr, g2 + i * D_, be2 + i * D_, i);
    }
}

// round 17
// speedup vs baseline: 2.2155x; 2.2155x over previous
#include <cuda_runtime.h>
#include <cuda_fp16.h>
#include <cstdint>

constexpr int L_  = 4;
constexpr int CB_ = 256;
constexpr int D_  = 512;
constexpr int B_  = 16;
constexpr int T_  = 4096;
constexpr int N_BT = B_ * T_;
constexpr float EPS_ = 1e-5f;

__device__ float g_z1[(size_t)B_ * D_ * T_];
__device__ float g_z2[(size_t)B_ * D_ * T_];
__device__ __align__(16) __half g_xp[(size_t)B_ * CB_ * T_];   // inter-layer x, fp16
__device__ __align__(16) __half g_w1s[L_ * D_ * CB_];
__device__ __align__(16) __half g_w2s[L_ * CB_ * D_];
__device__ float g_wds[L_ * D_ * 3];
__device__ float g_s1[L_ * D_];
__device__ float g_q1[L_ * D_];
__device__ float g_s2[L_ * D_];
__device__ float g_q2[L_ * D_];

__device__ __forceinline__ unsigned smem_u32(const void* p) {
    return (unsigned)__cvta_generic_to_shared(p);
}
__device__ __forceinline__ void ldsm4(unsigned* r, const void* p) {
    unsigned a = smem_u32(p);
    asm volatile("ldmatrix.sync.aligned.m8n8.x4.shared.b16 {%0,%1,%2,%3}, [%4];"
                 : "=r"(r[0]), "=r"(r[1]), "=r"(r[2]), "=r"(r[3]) : "r"(a));
}
__device__ __forceinline__ void ldsm4t(unsigned* r, const void* p) {
    unsigned a = smem_u32(p);
    asm volatile("ldmatrix.sync.aligned.m8n8.x4.trans.shared.b16 {%0,%1,%2,%3}, [%4];"
                 : "=r"(r[0]), "=r"(r[1]), "=r"(r[2]), "=r"(r[3]) : "r"(a));
}
__device__ __forceinline__ void mma16816(float* c, const unsigned* a, unsigned b0, unsigned b1) {
    asm volatile(
        "mma.sync.aligned.m16n8k16.row.col.f32.f16.f16.f32 "
        "{%0,%1,%2,%3},{%4,%5,%6,%7},{%8,%9},{%0,%1,%2,%3};"
        : "+f"(c[0]), "+f"(c[1]), "+f"(c[2]), "+f"(c[3])
        : "r"(a[0]), "r"(a[1]), "r"(a[2]), "r"(a[3]), "r"(b0), "r"(b1));
}
__device__ __forceinline__ uint32_t packh2(float a, float b) {
    __half2 t = __floats2half2_rn(a, b);
    return *reinterpret_cast<uint32_t*>(&t);
}

__global__ void prep_kernel(const float* __restrict__ w1,
                            const float* __restrict__ w2,
                            const float* __restrict__ wd) {
    int i = blockIdx.x * blockDim.x + threadIdx.x;
    constexpr int n1 = L_ * D_ * CB_;
    constexpr int n2 = L_ * CB_ * D_;
    constexpr int n3 = L_ * D_ * 3;
    constexpr int n4 = L_ * D_;
    if (i < n1) {
        float v = w1[i];
        g_w1s[i] = __float2half(v > 0.f ? 1.f : (v < 0.f ? -1.f : 0.f));
    } else if (i < n1 + n2) {
        float v = w2[i - n1];
        g_w2s[i - n1] = __float2half(v > 0.f ? 1.f : (v < 0.f ? -1.f : 0.f));
    } else if (i < n1 + n2 + n3) {
        float v = wd[i - n1 - n2];
        g_wds[i - n1 - n2] = v > 0.f ? 1.f : (v < 0.f ? -1.f : 0.f);
    } else if (i < n1 + n2 + n3 + 4 * n4) {
        int j = i - (n1 + n2 + n3);
        int which = j / n4, k = j % n4;
        if (which == 0) g_s1[k] = 0.f;
        else if (which == 1) g_q1[k] = 0.f;
        else if (which == 2) g_s2[k] = 0.f;
        else g_q2[k] = 0.f;
    }
}

// MODE 0: gemm1 L0 (fp32 x in) | 1: gemm1 L>0 (fp16 plane in) | 2: gemm2 mid (fp16 plane out) | 3: gemm2 last (fp32+resid out)
constexpr int BM = 128, BN = 128, BK = 32;
constexpr int WPITCH = 40, XPITCH = 136;
constexpr int WS_ELEMS = BM * WPITCH;
constexpr int XT_ELEMS = BK * XPITCH;
constexpr size_t GEMM_SMEM = (size_t)(2 * WS_ELEMS + 2 * XT_ELEMS) * sizeof(__half);

template<int MODE>
__global__ void __launch_bounds__(256, 2) gemm_kernel(
    const float* __restrict__ Xext, float* __restrict__ Oext,
    const float* __restrict__ bias, const float* __restrict__ aptr,
    const float* __restrict__ gch, const float* __restrict__ bech, int layer) {
    constexpr bool FIRST = (MODE <= 1);
    constexpr int Cin  = FIRST ? CB_ : D_;
    constexpr int Cout = FIRST ? D_ : CB_;
    constexpr int NITER = Cin / BK;
    const __half* __restrict__ W =
        (FIRST ? g_w1s : g_w2s) + (size_t)layer * Cin * Cout;

    extern __shared__ __align__(16) char sm_raw[];
    __half* WS = reinterpret_cast<__half*>(sm_raw);
    __half* XH = WS + 2 * WS_ELEMS;

    const int b  = blockIdx.z;
    const int m0 = blockIdx.y * BM;
    const int t0 = blockIdx.x * BN;
    const int tid  = threadIdx.x;
    const int warp = tid >> 5, lane = tid & 31;
    const int wm = (warp & 3) * 32;
    const int wn = (warp >> 2) * 64;

    const int wrow = tid >> 2, wcol = (tid & 3) * 8;   // W tile 128x32
    const int prow = tid >> 3, pcol = (tid & 7) * 16;  // fp16-plane tile 32x128

    const size_t xoff = (size_t)b * Cin * T_ + t0;
    const float* Xf = (MODE == 0) ? Xext + xoff : g_z2 + xoff;
    const __half* Xp = g_xp + xoff;

    float acc[2][8][4];
    #pragma unroll
    for (int i = 0; i < 2; i++)
        #pragma unroll
        for (int j = 0; j < 8; j++)
            #pragma unroll
            for (int r = 0; r < 4; r++) acc[i][j][r] = 0.f;

    const int grp = lane >> 3, l8 = lane & 7;
    const int bk_row = (grp & 1) * 8 + l8;
    const int bn_off = (grp >> 1) * 8;

    uint4 wreg0, wreg1;
    uint4 xp0, xp1;
    float4 xreg[4];
    float2 ssreg[4];
    constexpr float invN = 1.f / (float)N_BT;

    auto issue_loads = [&](int c0) {
        wreg0 = *reinterpret_cast<const uint4*>(W + (size_t)(m0 + wrow) * Cin + c0 + wcol);
        wreg1 = *reinterpret_cast<const uint4*>(W + (size_t)(m0 + wrow + 64) * Cin + c0 + wcol);
        if (MODE == 1) {
            const __half* src = Xp + (size_t)(c0 + prow) * T_ + pcol;
            xp0 = *reinterpret_cast<const uint4*>(src);
            xp1 = *reinterpret_cast<const uint4*>(src + 8);
        } else {
            #pragma unroll
            for (int rr = 0; rr < 4; rr++) {
                const int c = c0 + warp * 4 + rr;
                xreg[rr] = *reinterpret_cast<const float4*>(Xf + (size_t)c * T_ + lane * 4);
                if (MODE >= 2) {
                    ssreg[rr].x = g_s2[layer * D_ + c];
                    ssreg[rr].y = g_q2[layer * D_ + c];
                }
            }
        }
    };
    auto commit = [&](int c0, int p) {
        *reinterpret_cast<uint4*>(&WS[p * WS_ELEMS + wrow * WPITCH + wcol]) = wreg0;
        *reinterpret_cast<uint4*>(&WS[p * WS_ELEMS + (wrow + 64) * WPITCH + wcol]) = wreg1;
        if (MODE == 1) {
            __half* dst = &XH[p * XT_ELEMS + prow * XPITCH + pcol];
            *reinterpret_cast<uint4*>(dst) = xp0;
            *reinterpret_cast<uint4*>(dst + 8) = xp1;
        } else {
            #pragma unroll
            for (int rr = 0; rr < 4; rr++) {
                const int r = warp * 4 + rr;
                float4 v = xreg[rr];
                if (MODE >= 2) {
                    const int c = c0 + r;
                    const float mean = ssreg[rr].x * invN;
                    const float var  = ssreg[rr].y * invN - mean * mean;
                    const float s  = __ldg(gch + c) * rsqrtf(var + EPS_);
                    const float sh = __ldg(bech + c) - mean * s;
                    v.x = fmaf(s, v.x, sh); v.y = fmaf(s, v.y, sh);
                    v.z = fmaf(s, v.z, sh); v.w = fmaf(s, v.w, sh);
                }
                uint32_t* ph = reinterpret_cast<uint32_t*>(
                    &XH[p * XT_ELEMS + r * XPITCH + lane * 4]);
                ph[0] = packh2(v.x, v.y);
                ph[1] = packh2(v.z, v.w);
            }
        }
    };
    auto compute = [&](int p) {
        #pragma unroll
        for (int kk = 0; kk < 2; kk++) {
            const int k0 = kk * 16;
            unsigned a[2][4];
            #pragma unroll
            for (int mf = 0; mf < 2; mf++)
                ldsm4(a[mf], &WS[p * WS_ELEMS + (wm + mf * 16 + (lane & 15)) * WPITCH +
                                 k0 + (lane >> 4) * 8]);
            #pragma unroll
            for (int nb = 0; nb < 4; nb++) {
                unsigned bq[4];
                const int baddr = (k0 + bk_row) * XPITCH + wn + nb * 16 + bn_off;
                ldsm4t(bq, &XH[p * XT_ELEMS + baddr]);
                #pragma unroll
                for (int mf = 0; mf < 2; mf++) {
                    mma16816(acc[mf][2 * nb],     a[mf], bq[0], bq[1]);
                    mma16816(acc[mf][2 * nb + 1], a[mf], bq[2], bq[3]);
                }
            }
        }
    };

    issue_loads(0);
    commit(0, 0);
    __syncthreads();
    int p = 0;
    #pragma unroll 1
    for (int it = 0; it < NITER; ++it) {
        if (it + 1 < NITER) issue_loads((it + 1) * BK);
        compute(p);
        if (it + 1 < NITER) {
            commit((it + 1) * BK, p ^ 1);
            __syncthreads();
        }
        p ^= 1;
    }

    float av = 0.f;
    if (FIRST) av = __ldg(aptr);
    #pragma unroll
    for (int mf = 0; mf < 2; mf++) {
        #pragma unroll
        for (int half = 0; half < 2; half++) {
            const int row = m0 + wm + mf * 16 + (lane >> 2) + half * 8;
            const float bv = __ldg(bias + row);
            const size_t obase = ((size_t)b * Cout + row) * T_ + t0;
            float ps = 0.f, pss = 0.f;
            #pragma unroll
            for (int nf = 0; nf < 8; nf++) {
                const int col = wn + nf * 8 + (lane & 3) * 2;
                float v0 = acc[mf][nf][half * 2 + 0] + bv;
                float v1 = acc[mf][nf][half * 2 + 1] + bv;
                if (FIRST) {
                    v0 = v0 >= 0.f ? v0 : av * v0;
                    v1 = v1 >= 0.f ? v1 : av * v1;
                    ps += v0 + v1;
                    pss += fmaf(v0, v0, v1 * v1);
                    float2 o2; o2.x = v0; o2.y = v1;
                    *reinterpret_cast<float2*>(g_z1 + obase + col) = o2;
                } else if (MODE == 2) {
                    *reinterpret_cast<uint32_t*>(g_xp + obase + col) = packh2(v0, v1);
                } else {
                    const float2 rv = *reinterpret_cast<const float2*>(Xext + obase + col);
                    float2 o2; o2.x = v0 + rv.x; o2.y = v1 + rv.y;
                    *reinterpret_cast<float2*>(Oext + obase + col) = o2;
                }
            }
            if (FIRST) {
                ps  += __shfl_xor_sync(0xffffffffu, ps, 1);
                ps  += __shfl_xor_sync(0xffffffffu, ps, 2);
                pss += __shfl_xor_sync(0xffffffffu, pss, 1);
                pss += __shfl_xor_sync(0xffffffffu, pss, 2);
                if ((lane & 3) == 0) {
                    atomicAdd(&g_s1[layer * D_ + row], ps);
                    atomicAdd(&g_q1[layer * D_ + row], pss);
                }
            }
        }
    }
}

template<int DIL>
__global__ void __launch_bounds__(512) dwconv_kernel(const float* __restrict__ bdl,
                                                     const float* __restrict__ aptr,
                                                     const float* __restrict__ gch,
                                                     const float* __restrict__ bech,
                                                     int layer) {
    const int d = blockIdx.x, b = blockIdx.y;
    __shared__ float s[16 + T_];
    const float* __restrict__ zin = g_z1 + ((size_t)b * D_ + d) * T_;
    float* __restrict__ zo = g_z2 + ((size_t)b * D_ + d) * T_;

    constexpr float invN = 1.f / (float)N_BT;
    const float mean = g_s1[layer * D_ + d] * invN;
    const float var  = g_q1[layer * D_ + d] * invN - mean * mean;
    const float sc = __ldg(gch + d) * rsqrtf(var + EPS_);
    const float sh = __ldg(bech + d) - mean * sc;

    const int t0 = threadIdx.x * 8;
    #pragma unroll
    for (int h = 0; h < 2; h++) {
        float4 v = *reinterpret_cast<const float4*>(zin + t0 + h * 4);
        float4 w;
        w.x = fmaf(sc, v.x, sh); w.y = fmaf(sc, v.y, sh);
        w.z = fmaf(sc, v.z, sh); w.w = fmaf(sc, v.w, sh);
        *reinterpret_cast<float4*>(&s[16 + t0 + h * 4]) = w;
    }
    if (threadIdx.x < 4)
        *reinterpret_cast<float4*>(&s[threadIdx.x * 4]) = make_float4(0.f, 0.f, 0.f, 0.f);
    __syncthreads();

    const float w0 = g_wds[(layer * D_ + d) * 3 + 0];
    const float w1 = g_wds[(layer * D_ + d) * 3 + 1];
    const float w2 = g_wds[(layer * D_ + d) * 3 + 2];
    const float bb = __ldg(bdl + d);
    const float av = __ldg(aptr);

    float r[24];
    #pragma unroll
    for (int q = 0; q < 6; q++)
        *reinterpret_cast<float4*>(&r[q * 4]) =
            *reinterpret_cast<const float4*>(&s[t0 + q * 4]);

    float vv[8];
    float ps = 0.f, pss = 0.f;
    #pragma unroll
    for (int j = 0; j < 8; j++) {
        float acc = bb;
        acc = fmaf(w0, r[16 + j - 2 * DIL], acc);
        acc = fmaf(w1, r[16 + j - DIL], acc);
        acc = fmaf(w2, r[16 + j], acc);
        float v = acc >= 0.f ? acc : av * acc;
        vv[j] = v;
        ps += v;
        pss = fmaf(v, v, pss);
    }
    #pragma unroll
    for (int h = 0; h < 2; h++) {
        float4 o4;
        o4.x = vv[h * 4]; o4.y = vv[h * 4 + 1]; o4.z = vv[h * 4 + 2]; o4.w = vv[h * 4 + 3];
        *reinterpret_cast<float4*>(zo + t0 + h * 4) = o4;
    }

    #pragma unroll
    for (int o = 16; o; o >>= 1) {
        ps  += __shfl_down_sync(0xffffffffu, ps, o);
        pss += __shfl_down_sync(0xffffffffu, pss, o);
    }
    __shared__ float ssum[16], ssq[16];
    const int warp = threadIdx.x >> 5, lane = threadIdx.x & 31;
    if (lane == 0) { ssum[warp] = ps; ssq[warp] = pss; }
    __syncthreads();
    if (warp == 0) {
        ps  = lane < 16 ? ssum[lane] : 0.f;
        pss = lane < 16 ? ssq[lane] : 0.f;
        #pragma unroll
        for (int o = 8; o; o >>= 1) {
            ps  += __shfl_down_sync(0xffffffffu, ps, o);
            pss += __shfl_down_sync(0xffffffffu, pss, o);
        }
        if (lane == 0) {
            atomicAdd(&g_s2[layer * D_ + d], ps);
            atomicAdd(&g_q2[layer * D_ + d], pss);
        }
    }
}

extern "C" void kernel_launch(void* const* d_in, const int* in_sizes, int n_in,
                              void* d_out, int out_size) {
    (void)in_sizes; (void)n_in; (void)out_size;
    const float* x   = (const float*)d_in[0];
    const float* w1  = (const float*)d_in[1];
    const float* b1  = (const float*)d_in[2];
    const float* a1  = (const float*)d_in[3];
    const float* g1  = (const float*)d_in[4];
    const float* be1 = (const float*)d_in[5];
    const float* wd  = (const float*)d_in[6];
    const float* bd  = (const float*)d_in[7];
    const float* a2  = (const float*)d_in[8];
    const float* g2  = (const float*)d_in[9];
    const float* be2 = (const float*)d_in[10];
    const float* w2  = (const float*)d_in[11];
    const float* b2  = (const float*)d_in[12];
    float* out = (float*)d_out;

    static bool attr_done = false;
    if (!attr_done) {
        cudaFuncSetAttribute(gemm_kernel<0>, cudaFuncAttributeMaxDynamicSharedMemorySize, (int)GEMM_SMEM);
        cudaFuncSetAttribute(gemm_kernel<1>, cudaFuncAttributeMaxDynamicSharedMemorySize, (int)GEMM_SMEM);
        cudaFuncSetAttribute(gemm_kernel<2>, cudaFuncAttributeMaxDynamicSharedMemorySize, (int)GEMM_SMEM);
        cudaFuncSetAttribute(gemm_kernel<3>, cudaFuncAttributeMaxDynamicSharedMemorySize, (int)GEMM_SMEM);
        attr_done = true;
    }

    constexpr int prep_total = L_ * D_ * CB_ + L_ * CB_ * D_ + L_ * D_ * 3 + 4 * L_ * D_;
    prep_kernel<<<(prep_total + 255) / 256, 256>>>(w1, w2, wd);

    dim3 gg1(T_ / BN, D_ / BM, B_);    // 32 x 4 x 16
    dim3 gg2(T_ / BN, CB_ / BM, B_);   // 32 x 2 x 16
    dim3 gdw(D_, B_);

    for (int i = 0; i < L_; i++) {
        if (i == 0)
            gemm_kernel<0><<<gg1, 256, GEMM_SMEM>>>(x, nullptr, b1, a1, nullptr, nullptr, 0);
        else
            gemm_kernel<1><<<gg1, 256, GEMM_SMEM>>>(nullptr, nullptr, b1 + i * D_, a1 + i, nullptr, nullptr, i);
        switch (i) {
            case 0: dwconv_kernel<1><<<gdw, 512>>>(bd + i * D_, a2 + i, g1 + i * D_, be1 + i * D_, i); break;
            case 1: dwconv_kernel<2><<<gdw, 512>>>(bd + i * D_, a2 + i, g1 + i * D_, be1 + i * D_, i); break;
            case 2: dwconv_kernel<4><<<gdw, 512>>>(bd + i * D_, a2 + i, g1 + i * D_, be1 + i * D_, i); break;
            default: dwconv_kernel<8><<<gdw, 512>>>(bd + i * D_, a2 + i, g1 + i * D_, be1 + i * D_, i); break;
        }
        if (i < L_ - 1)
            gemm_kernel<2><<<gg2, 256, GEMM_SMEM>>>(nullptr, nullptr, b2 + i * CB_, nullptr, g2 + i * D_, be2 + i * D_, i);
        else
            gemm_kernel<3><<<gg2, 256, GEMM_SMEM>>>(x, out, b2 + i * CB_, nullptr, g2 + i * D_, be2 + i * D_, i);
    }
}